// round 8
// baseline (speedup 1.0000x reference)
#include <cuda_runtime.h>

#define DIMN 32
#define TPB 256

__device__ unsigned long long g_wp[DIMN];

__device__ __forceinline__ unsigned long long pack2(float lo, float hi) {
    unsigned long long r;
    asm("mov.b64 %0, {%1, %2};" : "=l"(r) : "f"(lo), "f"(hi));
    return r;
}
__device__ __forceinline__ void unpack2(unsigned long long v, float& lo, float& hi) {
    asm("mov.b64 {%0, %1}, %2;" : "=f"(lo), "=f"(hi) : "l"(v));
}
__device__ __forceinline__ unsigned long long fma2(unsigned long long a,
                                                   unsigned long long b,
                                                   unsigned long long c) {
    unsigned long long d;
    asm("fma.rn.f32x2 %0, %1, %2, %3;" : "=l"(d) : "l"(a), "l"(b), "l"(c));
    return d;
}

__global__ void pack_w_kernel(const float* __restrict__ w) {
    int k = threadIdx.x;
    if (k < DIMN) {
        float wk = w[k];
        g_wp[k] = pack2(wk, wk);
    }
}

__global__ __launch_bounds__(TPB, 4) void poly_persist2_kernel(
    const float* __restrict__ x,
    float* __restrict__ out,
    int n_vec4)
{
    __shared__ unsigned long long s_wp[DIMN];
    if (threadIdx.x < DIMN) s_wp[threadIdx.x] = g_wp[threadIdx.x];
    __syncthreads();

    const float4* __restrict__ x4 = reinterpret_cast<const float4*>(x);
    float4* __restrict__ o4 = reinterpret_cast<float4*>(out);

    const int stride = gridDim.x * (2 * TPB);   // float4s consumed per sweep
    int base = blockIdx.x * (2 * TPB) + threadIdx.x;

    // ---- prologue: load first pair of float4s ----
    int iA = base;
    int iB = base + TPB;
    float4 curA = (iA < n_vec4) ? __ldg(&x4[iA]) : make_float4(0.f, 0.f, 0.f, 0.f);
    float4 curB = (iB < n_vec4) ? __ldg(&x4[iB]) : make_float4(0.f, 0.f, 0.f, 0.f);

    while (iA < n_vec4) {
        // ---- prefetch next sweep BEFORE the compute burst ----
        int nA = iA + stride;
        int nB = iB + stride;
        float4 nxtA = (nA < n_vec4) ? __ldg(&x4[nA]) : make_float4(0.f, 0.f, 0.f, 0.f);
        float4 nxtB = (nB < n_vec4) ? __ldg(&x4[nB]) : make_float4(0.f, 0.f, 0.f, 0.f);

        // ---- opaque coefficient pointer: forces per-iteration LDS,
        //      prevents ptxas hoisting coefficients into registers ----
        const unsigned long long* wp = s_wp;
        asm("" : "+l"(wp));

        // ---- 4 independent packed Horner chains (named scalars only) ----
        unsigned long long p0 = pack2(curA.x, curA.y);
        unsigned long long p1 = pack2(curA.z, curA.w);
        unsigned long long p2 = pack2(curB.x, curB.y);
        unsigned long long p3 = pack2(curB.z, curB.w);

        unsigned long long a0 = wp[DIMN - 1];
        unsigned long long a1 = a0, a2 = a0, a3 = a0;

#pragma unroll
        for (int k = DIMN - 2; k >= 0; --k) {
            unsigned long long wk = wp[k];
            a0 = fma2(a0, p0, wk);
            a1 = fma2(a1, p1, wk);
            a2 = fma2(a2, p2, wk);
            a3 = fma2(a3, p3, wk);
        }

        // ---- store current sweep ----
        float4 ov;
        if (iA < n_vec4) {
            unpack2(a0, ov.x, ov.y); unpack2(a1, ov.z, ov.w);
            o4[iA] = ov;
        }
        if (iB < n_vec4) {
            unpack2(a2, ov.x, ov.y); unpack2(a3, ov.z, ov.w);
            o4[iB] = ov;
        }

        curA = nxtA; curB = nxtB;
        iA = nA; iB = nB;
    }
}

extern "C" void kernel_launch(void* const* d_in, const int* in_sizes, int n_in,
                              void* d_out, int out_size) {
    const float* x = (const float*)d_in[0];
    const float* w = (const float*)d_in[1];
    float* out = (float*)d_out;

    int n = in_sizes[0];            // 4194304
    int n_vec4 = n / 4;             // 1048576 float4s

    int sms = 148;
    cudaDeviceGetAttribute(&sms, cudaDevAttrMultiProcessorCount, 0);
    int blocks = sms * 3;           // exactly resident (regs<=64, 4 blocks/SM cap)
    int max_blocks = (n_vec4 + 2 * TPB - 1) / (2 * TPB);
    if (blocks > max_blocks) blocks = max_blocks;

    pack_w_kernel<<<1, DIMN>>>(w);
    poly_persist2_kernel<<<blocks, TPB>>>(x, out, n_vec4);
}

// round 9
// speedup vs baseline: 1.0312x; 1.0312x over previous
#include <cuda_runtime.h>

#define DIMN 32
#define TPB 256
#define TILE_F4 (TPB * 4)   // float4s per tile (per block per trip)

__device__ __forceinline__ unsigned long long pack2(float lo, float hi) {
    unsigned long long r;
    asm("mov.b64 %0, {%1, %2};" : "=l"(r) : "f"(lo), "f"(hi));
    return r;
}
__device__ __forceinline__ void unpack2(unsigned long long v, float& lo, float& hi) {
    asm("mov.b64 {%0, %1}, %2;" : "=f"(lo), "=f"(hi) : "l"(v));
}
__device__ __forceinline__ unsigned long long fma2(unsigned long long a,
                                                   unsigned long long b,
                                                   unsigned long long c) {
    unsigned long long d;
    asm("fma.rn.f32x2 %0, %1, %2, %3;" : "=l"(d) : "l"(a), "l"(b), "l"(c));
    return d;
}

__global__ __launch_bounds__(TPB) void poly_fused_kernel(
    const float* __restrict__ x,
    const float* __restrict__ w,
    float* __restrict__ out,
    int n_vec4,
    int n_tiles)
{
    // In-kernel coefficient packing: no separate pack kernel / extra launch.
    __shared__ unsigned long long s_wp[DIMN];
    if (threadIdx.x < DIMN) {
        float wk = __ldg(&w[threadIdx.x]);
        s_wp[threadIdx.x] = pack2(wk, wk);
    }
    __syncthreads();

    const float4* __restrict__ x4 = reinterpret_cast<const float4*>(x);
    float4* __restrict__ o4 = reinterpret_cast<float4*>(out);

    // Grid-stride over tiles; grid sized so every block gets exactly 2 tiles.
    for (int t = blockIdx.x; t < n_tiles; t += gridDim.x) {
        int base4 = t * TILE_F4 + threadIdx.x;
        int i0 = base4;
        int i1 = base4 + TPB;
        int i2 = base4 + 2 * TPB;
        int i3 = base4 + 3 * TPB;

        // Front-batched coalesced loads (MLP=4).
        float4 xv0 = (i0 < n_vec4) ? __ldg(&x4[i0]) : make_float4(0.f, 0.f, 0.f, 0.f);
        float4 xv1 = (i1 < n_vec4) ? __ldg(&x4[i1]) : make_float4(0.f, 0.f, 0.f, 0.f);
        float4 xv2 = (i2 < n_vec4) ? __ldg(&x4[i2]) : make_float4(0.f, 0.f, 0.f, 0.f);
        float4 xv3 = (i3 < n_vec4) ? __ldg(&x4[i3]) : make_float4(0.f, 0.f, 0.f, 0.f);

        // Opaque coefficient pointer: forbids hoisting 32 u64 coefficients
        // into registers across the tile loop (R6 failure mode).
        const unsigned long long* wp = s_wp;
        asm("" : "+l"(wp));

        // 8 independent packed Horner chains — named scalars only (no arrays:
        // R7 failure mode was u64 arrays -> local-memory spill).
        unsigned long long p0 = pack2(xv0.x, xv0.y);
        unsigned long long p1 = pack2(xv0.z, xv0.w);
        unsigned long long p2 = pack2(xv1.x, xv1.y);
        unsigned long long p3 = pack2(xv1.z, xv1.w);
        unsigned long long p4 = pack2(xv2.x, xv2.y);
        unsigned long long p5 = pack2(xv2.z, xv2.w);
        unsigned long long p6 = pack2(xv3.x, xv3.y);
        unsigned long long p7 = pack2(xv3.z, xv3.w);

        unsigned long long a0 = wp[DIMN - 1];
        unsigned long long a1 = a0, a2 = a0, a3 = a0;
        unsigned long long a4 = a0, a5 = a0, a6 = a0, a7 = a0;

#pragma unroll
        for (int k = DIMN - 2; k >= 0; --k) {
            unsigned long long wk = wp[k];   // one broadcast LDS.64 feeds 8 FFMA2
            a0 = fma2(a0, p0, wk);
            a1 = fma2(a1, p1, wk);
            a2 = fma2(a2, p2, wk);
            a3 = fma2(a3, p3, wk);
            a4 = fma2(a4, p4, wk);
            a5 = fma2(a5, p5, wk);
            a6 = fma2(a6, p6, wk);
            a7 = fma2(a7, p7, wk);
        }

        float4 ov;
        if (i0 < n_vec4) { unpack2(a0, ov.x, ov.y); unpack2(a1, ov.z, ov.w); o4[i0] = ov; }
        if (i1 < n_vec4) { unpack2(a2, ov.x, ov.y); unpack2(a3, ov.z, ov.w); o4[i1] = ov; }
        if (i2 < n_vec4) { unpack2(a4, ov.x, ov.y); unpack2(a5, ov.z, ov.w); o4[i2] = ov; }
        if (i3 < n_vec4) { unpack2(a6, ov.x, ov.y); unpack2(a7, ov.z, ov.w); o4[i3] = ov; }
    }
}

extern "C" void kernel_launch(void* const* d_in, const int* in_sizes, int n_in,
                              void* d_out, int out_size) {
    const float* x = (const float*)d_in[0];
    const float* w = (const float*)d_in[1];
    float* out = (float*)d_out;

    int n = in_sizes[0];                       // 4194304
    int n_vec4 = n / 4;                        // 1048576 float4s
    int n_tiles = (n_vec4 + TILE_F4 - 1) / TILE_F4;   // 1024

    // Exactly 2 tiles per block -> uniform work, tail-free second trip.
    int blocks = (n_tiles + 1) / 2;            // 512
    if (blocks < 1) blocks = 1;

    poly_fused_kernel<<<blocks, TPB>>>(x, w, out, n_vec4, n_tiles);
}